// round 7
// baseline (speedup 1.0000x reference)
#include <cuda_runtime.h>
#include <cstdint>

#define Nn 32
#define Cc 256
#define Hh 32
#define Ww 32
#define HW (Hh*Ww)
#define NCHW (Nn*Cc*Hh*Ww)
#define NPIX (Nn*Hh*Ww)
#define NCHUNK 36

// ---------------- scratch (device globals; no allocation) ----------------
__device__ uint32_t           g_xbits[NPIX*8];        // channel-packed sign bits of current conv input
__device__ uint32_t           g_wchan[2][Cc*72];      // channel-packed weights [o][j=0..8][k=0..7]
__device__ unsigned long long g_wrT[2][NCHUNK*Cc];    // r-packed weights, transposed [chunk][o]
__device__ int16_t            g_y1[NCHW];             // conv1 output (clipped int)
__device__ int16_t            g_y2[NCHW];             // conv2 output (clipped int, pre-residual)
__device__ int                g_s1[Cc], g_q1[Cc];     // conv1 channel stats (exact int32)
__device__ float              g_A1[Cc], g_B1[Cc];     // bn1 sign-test coefs
__device__ double             g_S2[Cc], g_Q2[Cc];     // bn2 channel stats
__device__ float              g_A2[Cc], g_B2[Cc];
__device__ unsigned long long g_vmask[9*NCHUNK];      // per boundary-class valid-bit mask per chunk
__device__ int                g_V[9*NCHUNK];          // valid counts
__device__ int                g_SV[9], g_NO[9];       // per-class: sum V, count of odd-V chunks
__device__ float              g_regbase;              // 3*G/1024

// ---------------- init: geometric tables + stat reset + regularizer ----------------
__global__ void k_init() {
    int t = threadIdx.x;
    if (t < 9*NCHUNK) {
        int cls = t / NCHUNK, i = t % NCHUNK;
        int ht = cls / 3, wt = cls % 3;
        int r = 64*i, c = r/9, j = r - 9*c;
        unsigned long long m = 0;
        for (int b = 0; b < 64; b++) {
            int kh = j/3, kw = j - 3*kh;
            bool inval = (ht==0 && kh==0) || (ht==2 && kh==2) ||
                         (wt==0 && kw==0) || (wt==2 && kw==2);
            if (!inval) m |= 1ull << b;
            if (++j == 9) { j = 0; c++; }
        }
        g_vmask[t] = m;
        g_V[t] = __popcll(m);
    }
    if (t < Cc) { g_s1[t] = 0; g_q1[t] = 0; g_S2[t] = 0.0; g_Q2[t] = 0.0; }
    __syncthreads();
    if (t < 9) {
        int sv = 0, no = 0;
        for (int i = 0; i < NCHUNK; i++) { int V = g_V[t*NCHUNK + i]; sv += V; no += V & 1; }
        g_SV[t] = sv; g_NO[t] = no;
    }
    if (t == 0) {
        // reg = r1 + 2*r2 = 3 * sum_{chunks,pixels} parity / (H*W); parity is geometric
        long long G = 0;
        int npix[3] = {1, 30, 1};
        for (int cls = 0; cls < 9; cls++) {
            long long cnt = (long long)npix[cls/3] * npix[cls%3];
            for (int i = 0; i < NCHUNK; i++)
                G += cnt * (long long)(g_V[cls*NCHUNK + i] & 1);
        }
        g_regbase = 3.0f * (float)G / (float)HW;
    }
}

// ---------------- weight packing: both layouts, both convs, one kernel ----------------
__global__ void k_packw(const float* __restrict__ w1, const float* __restrict__ w2) {
    int o    = blockIdx.x & 255;
    int slot = blockIdx.x >> 8;
    const float* w = slot ? w2 : w1;
    int warp = threadIdx.x >> 5, lane = threadIdx.x & 31;

    // r-packed transposed: bit b of word [i][o] = sign(w[o, r=64i+b])
    for (int i = warp; i < NCHUNK; i += 8) {
        unsigned lo = __ballot_sync(0xffffffffu, w[o*2304 + 64*i + lane]      >= 0.f);
        unsigned hi = __ballot_sync(0xffffffffu, w[o*2304 + 64*i + 32 + lane] >= 0.f);
        if (lane == 0)
            g_wrT[slot][i*Cc + o] = (unsigned long long)lo | ((unsigned long long)hi << 32);
    }

    // channel-packed: word [o][j][c>>5], bit (c&31)
    int c = threadIdx.x;
    float v[9];
    #pragma unroll
    for (int j = 0; j < 9; j++) v[j] = w[o*2304 + c*9 + j];
    #pragma unroll
    for (int j = 0; j < 9; j++) {
        unsigned b = __ballot_sync(0xffffffffu, v[j] >= 0.f);
        if (lane == 0) g_wchan[slot][o*72 + j*8 + (c >> 5)] = b;
    }
}

// ---------------- input packing ----------------
__global__ void k_pack_x(const float* __restrict__ x) {
    int n = blockIdx.x >> 5, h = blockIdx.x & 31;
    int w = threadIdx.x & 31, k = threadIdx.x >> 5;
    const float* base = x + ((size_t)(n*Cc + k*32) * Hh + h) * Ww + w;
    uint32_t word = 0;
    #pragma unroll 8
    for (int cc = 0; cc < 32; cc++)
        if (base[(size_t)cc * HW] >= 0.f) word |= 1u << cc;
    g_xbits[((n*Hh + h)*Ww + w)*8 + k] = word;
}

// pack sign of bn1(hardtanh preserves sign): bit = (y*A1[c] + B1[c] >= 0)
__global__ void k_pack2() {
    int n = blockIdx.x >> 5, h = blockIdx.x & 31;
    int w = threadIdx.x & 31, k = threadIdx.x >> 5;
    const int16_t* base = g_y1 + ((size_t)(n*Cc + k*32) * Hh + h) * Ww + w;
    uint32_t word = 0;
    #pragma unroll 8
    for (int cc = 0; cc < 32; cc++) {
        int c = k*32 + cc;
        float y = (float)base[(size_t)cc * HW];
        if (fmaf(y, g_A1[c], g_B1[c]) >= 0.f) word |= 1u << cc;
    }
    g_xbits[((n*Hh + h)*Ww + w)*8 + k] = word;
}

// ---------------- CSA helpers: single-LOP3 xor3 / majority ----------------
__device__ __forceinline__ uint32_t lop3_x3(uint32_t a, uint32_t b, uint32_t c) {
    uint32_t r;
    asm("lop3.b32 %0, %1, %2, %3, 0x96;" : "=r"(r) : "r"(a), "r"(b), "r"(c));
    return r;   // a ^ b ^ c
}
__device__ __forceinline__ uint32_t lop3_maj(uint32_t a, uint32_t b, uint32_t c) {
    uint32_t r;
    asm("lop3.b32 %0, %1, %2, %3, 0xE8;" : "=r"(r) : "r"(a), "r"(b), "r"(c));
    return r;   // majority(a,b,c)
}

// popcount of 8 XNOR-diff words via 4 full-adders: 4 POPC instead of 8.
// Sum popc(v0..v7) = popc(s3) + popc(v7) + 2*popc(s4) + 4*popc(c4)   (exact)
__device__ __forceinline__ int tap_count(uint4 xa, uint4 xb, uint4 wa, uint4 wb) {
    uint32_t v0 = xa.x ^ wa.x, v1 = xa.y ^ wa.y, v2 = xa.z ^ wa.z, v3 = xa.w ^ wa.w;
    uint32_t v4 = xb.x ^ wb.x, v5 = xb.y ^ wb.y, v6 = xb.z ^ wb.z, v7 = xb.w ^ wb.w;
    uint32_t sA = lop3_x3(v0, v1, v2), cA = lop3_maj(v0, v1, v2);
    uint32_t sB = lop3_x3(v3, v4, v5), cB = lop3_maj(v3, v4, v5);
    uint32_t s3 = lop3_x3(sA, sB, v6), c3 = lop3_maj(sA, sB, v6);
    uint32_t s4 = lop3_x3(cA, cB, c3), c4 = lop3_maj(cA, cB, c3);
    return __popc(s3) + __popc(v7) + 2*__popc(s4) + 4*__popc(c4);
}

// ---------------- interior conv: 2-row strip, 8-way o-blocking, CSA popcount, 1-wave grid ----------------
// quantization is an exact no-op for interior pixels (psum always even, |psum|<=64)
template<int MODE>   // 1: write y1 int16 + int stats; 2: write y2 int16 + float stats on z=acc+res
__global__ void __launch_bounds__(256, 4) k_conv_int(const float* __restrict__ x0res, int slot) {
    int n = blockIdx.x / 15, hp = blockIdx.x % 15;
    int h0 = 1 + 2*hp;                       // rows h0, h0+1; halo rows h0-1..h0+2
    __shared__ __align__(16) uint32_t sx[4][Ww][8];      // 4 KB
    __shared__ __align__(16) uint32_t sw[64*72];         // 18 KB: one 64-o stage of weights
    int t = threadIdx.x;
    ((uint4*)sx)[t] = ((const uint4*)(g_xbits + (size_t)(n*Hh + (h0-1)) * Ww * 8))[t];

    int w = t & 31, warp = t >> 5;
    int wl = (w > 0) ? w-1 : 0;
    int wr = (w < 31) ? w+1 : 31;
    const int wcol[3] = {wl, w, wr};
    bool valid = (w >= 1 && w <= 30);
    size_t base0 = (((size_t)n*Cc*Hh) + h0) * Ww + w;   // + o*HW

    for (int stage = 0; stage < 4; stage++) {
        __syncthreads();   // protect sw reuse (also covers initial sx fill)
        // cooperative load of 64 o's weights: 64*72 words = 1152 uint4
        const uint4* gsrc = (const uint4*)(g_wchan[slot] + stage*64*72);
        #pragma unroll
        for (int i = 0; i < 1152/256; i++) ((uint4*)sw)[t + i*256] = gsrc[t + i*256];
        if (t < 128) ((uint4*)sw)[1024 + t] = gsrc[1024 + t];
        __syncthreads();

        int ob = warp*8;   // this warp's 8 o's within the stage
        // packed accumulators: low 16 = row0 popc-sum, high 16 = row1 (each <= 2304, no carry)
        int s01[8];
        #pragma unroll
        for (int oo = 0; oo < 8; oo++) s01[oo] = 0;

        #pragma unroll
        for (int j = 0; j < 9; j++) {
            int rr = j / 3;
            int wc = wcol[j % 3];
            const uint32_t* xp0 = &sx[rr][wc][0];
            uint4 xa = *(const uint4*)xp0;
            uint4 xb = *(const uint4*)(xp0 + 4);
            const uint32_t* xp1 = &sx[rr+1][wc][0];
            uint4 ya = *(const uint4*)xp1;
            uint4 yb = *(const uint4*)(xp1 + 4);
            #pragma unroll
            for (int oo = 0; oo < 8; oo++) {
                const uint4* wp = (const uint4*)(&sw[(ob + oo)*72 + j*8]);
                uint4 wa = wp[0];
                uint4 wb = wp[1];
                int t0 = tap_count(xa, xb, wa, wb);
                int t1 = tap_count(ya, yb, wa, wb);
                s01[oo] += t0 + (t1 << 16);
            }
        }

        #pragma unroll
        for (int oo = 0; oo < 8; oo++) {
            int o = stage*64 + ob + oo;
            int s0 = s01[oo] & 0xFFFF;
            int s1 = s01[oo] >> 16;
            int a0 = min(max(2304 - 2*s0, -254), 254);
            int a1 = min(max(2304 - 2*s1, -254), 254);
            size_t idx = base0 + (size_t)o * HW;
            if (MODE == 1) {
                if (valid) { g_y1[idx] = (int16_t)a0; g_y1[idx + Ww] = (int16_t)a1; }
                int vs = valid ? (a0 + a1) : 0;
                int vq = valid ? (a0*a0 + a1*a1) : 0;
                vs = __reduce_add_sync(0xffffffffu, vs);
                vq = __reduce_add_sync(0xffffffffu, vq);
                if (w == 0) { atomicAdd(&g_s1[o], vs); atomicAdd(&g_q1[o], vq); }
            } else {
                float z0 = 0.f, z1 = 0.f;
                if (valid) {
                    z0 = (float)a0 + x0res[idx];
                    z1 = (float)a1 + x0res[idx + Ww];
                    g_y2[idx] = (int16_t)a0; g_y2[idx + Ww] = (int16_t)a1;
                }
                float fs = z0 + z1, fq = z0*z0 + z1*z1;
                #pragma unroll
                for (int d = 16; d; d >>= 1) {
                    fs += __shfl_xor_sync(0xffffffffu, fs, d);
                    fq += __shfl_xor_sync(0xffffffffu, fq, d);
                }
                if (w == 0) { atomicAdd(&g_S2[o], (double)fs); atomicAdd(&g_Q2[o], (double)fq); }
            }
        }
    }
}

// ---------------- boundary conv: whole-side blocks, shared weight loads, packed accs ----------------
// per chunk: psum_q = psum + corr, corr = 0 if V even else 2*((P&1)^v2) - 1  (banker's rounding, exact)
// acc_final = SV - 2*sumP + 2*ccnt - Nodd
__device__ __forceinline__ void bstep(uint32_t& acc, unsigned long long s, unsigned long long w64,
                                      unsigned long long m, uint32_t v2, uint32_t od) {
    unsigned long long X = (s ^ w64) & m;        // 2x LOP3
    uint32_t P = __popcll(X);                    // 2x POPC + add
    uint32_t tt = (P ^ v2) & od;                 // 1x LOP3 (bit0 only; v2,od in {0,1})
    acc += P + (tt << 16);
}

template<int MODE>
__global__ void __launch_bounds__(128) k_conv_bnd(const float* __restrict__ x0res, int slot) {
    int blk   = blockIdx.x;          // 0..255 = n(5b) | side(2b) | ohalf(1b)
    int ohalf = blk & 1;
    int side  = (blk >> 1) & 3;      // 0: h=0 row; 1: h=31; 2: w=0 col; 3: w=31
    int n     = blk >> 3;
    int P     = (side < 2) ? 32 : 30;

    __shared__ unsigned long long sxr[32][NCHUNK];
    int t = threadIdx.x, warp = t >> 5, lane = t & 31;

    // build r-ordered chunk words for every pixel of this side (warp-parallel via ballot)
    for (int p = warp; p < P; p += 4) {
        int h, w;
        if      (side == 0) { h = 0;     w = p; }
        else if (side == 1) { h = 31;    w = p; }
        else if (side == 2) { h = 1 + p; w = 0; }
        else                { h = 1 + p; w = 31; }
        for (int i = 0; i < NCHUNK; i++) {
            int r0 = 64*i + lane;
            int c0 = r0 / 9, j0 = r0 - 9*c0;
            int kh0 = j0 / 3, kw0 = j0 - 3*kh0;
            int hh0 = min(max(h + kh0 - 1, 0), 31), ww0 = min(max(w + kw0 - 1, 0), 31);
            unsigned lo = __ballot_sync(0xffffffffu,
                (g_xbits[((n*Hh + hh0)*Ww + ww0)*8 + (c0 >> 5)] >> (c0 & 31)) & 1u);
            int r1 = r0 + 32;
            int c1 = r1 / 9, j1 = r1 - 9*c1;
            int kh1 = j1 / 3, kw1 = j1 - 3*kh1;
            int hh1 = min(max(h + kh1 - 1, 0), 31), ww1 = min(max(w + kw1 - 1, 0), 31);
            unsigned hi = __ballot_sync(0xffffffffu,
                (g_xbits[((n*Hh + hh1)*Ww + ww1)*8 + (c1 >> 5)] >> (c1 & 31)) & 1u);
            if (lane == 0)
                sxr[p][i] = (unsigned long long)lo | ((unsigned long long)hi << 32);
        }
    }
    __syncthreads();

    int o = ohalf*128 + t;
    // class assignment per side
    int clsE, clsC0, clsC2;
    if      (side == 0) { clsE = 1; clsC0 = 0; clsC2 = 2; }
    else if (side == 1) { clsE = 7; clsC0 = 6; clsC2 = 8; }
    else if (side == 2) { clsE = 3; clsC0 = 3; clsC2 = 3; }
    else                { clsE = 5; clsC0 = 5; clsC2 = 5; }
    bool corner = (side < 2);

    uint32_t acc[32];
    #pragma unroll
    for (int p = 0; p < 32; p++) acc[p] = 0;

    const unsigned long long* wr = g_wrT[slot];
    for (int i = 0; i < NCHUNK; i++) {
        unsigned long long w64 = wr[i*Cc + o];
        unsigned long long mE  = g_vmask[clsE*NCHUNK + i];
        int VE = g_V[clsE*NCHUNK + i];
        uint32_t v2E = (VE >> 1) & 1, odE = VE & 1;
        if (corner) {
            unsigned long long m0 = g_vmask[clsC0*NCHUNK + i];
            int V0 = g_V[clsC0*NCHUNK + i];
            bstep(acc[0], sxr[0][i], w64, m0, (V0 >> 1) & 1, V0 & 1);
            unsigned long long m2 = g_vmask[clsC2*NCHUNK + i];
            int V2 = g_V[clsC2*NCHUNK + i];
            bstep(acc[31], sxr[31][i], w64, m2, (V2 >> 1) & 1, V2 & 1);
            #pragma unroll
            for (int p = 1; p < 31; p++) bstep(acc[p], sxr[p][i], w64, mE, v2E, odE);
        } else {
            #pragma unroll
            for (int p = 0; p < 30; p++) bstep(acc[p], sxr[p][i], w64, mE, v2E, odE);
        }
    }

    // finalize: per-pixel value, write, batched stats
    int svE = g_SV[clsE], noE = g_NO[clsE];
    int sv0 = g_SV[clsC0], no0 = g_NO[clsC0];
    int sv2 = g_SV[clsC2], no2 = g_NO[clsC2];
    int   sumS = 0, sumQ = 0;
    double dz = 0.0, dq = 0.0;
    #pragma unroll
    for (int p = 0; p < 32; p++) {
        if (p < P) {
            int sv = svE, no = noE;
            if (corner && p == 0)  { sv = sv0; no = no0; }
            if (corner && p == 31) { sv = sv2; no = no2; }
            int sumP = (int)(acc[p] & 0xFFFF);
            int ccnt = (int)(acc[p] >> 16);
            int a = sv - 2*sumP + 2*ccnt - no;
            a = min(max(a, -254), 254);
            int h, w;
            if      (side == 0) { h = 0;     w = p; }
            else if (side == 1) { h = 31;    w = p; }
            else if (side == 2) { h = 1 + p; w = 0; }
            else                { h = 1 + p; w = 31; }
            size_t idx = ((size_t)(n*Cc + o) * Hh + h) * Ww + w;
            if (MODE == 1) {
                g_y1[idx] = (int16_t)a;
                sumS += a; sumQ += a*a;
            } else {
                float z = (float)a + x0res[idx];
                g_y2[idx] = (int16_t)a;
                dz += (double)z; dq += (double)(z*z);
            }
        }
    }
    if (MODE == 1) { atomicAdd(&g_s1[o], sumS); atomicAdd(&g_q1[o], sumQ); }
    else           { atomicAdd(&g_S2[o], dz);   atomicAdd(&g_Q2[o], dq); }
}

// ---------------- BN coefficient kernels ----------------
__global__ void k_coef1(const float* __restrict__ gamma, const float* __restrict__ beta) {
    int o = threadIdx.x;
    double m   = (double)g_s1[o] / (double)(Nn*HW);
    double var = (double)g_q1[o] / (double)(Nn*HW) - m*m;
    float inv  = (float)(1.0 / sqrt(var + 1e-5));
    float A = gamma[o] * inv;
    g_A1[o] = A;
    g_B1[o] = beta[o] - (float)m * A;
}

__global__ void k_coef2(const float* __restrict__ gamma, const float* __restrict__ beta) {
    int o = threadIdx.x;
    double m   = g_S2[o] / (double)(Nn*HW);
    double var = g_Q2[o] / (double)(Nn*HW) - m*m;
    float inv  = (float)(1.0 / sqrt(var + 1e-5));
    float A = gamma[o] * inv;
    g_A2[o] = A;
    g_B2[o] = beta[o] - (float)m * A;
}

// ---------------- finalize: z = acc2 + residual, bn2 + hardtanh, regularizer scalar ----------------
__global__ void k_final(float* __restrict__ out, const float* __restrict__ reg0,
                        const float* __restrict__ x0, int out_size) {
    size_t v = (size_t)blockIdx.x * 256 + threadIdx.x;   // 4-element group index
    size_t idx = v * 4;
    if (idx < (size_t)NCHW) {
        int o = (int)((idx >> 10) & 255);
        float A = g_A2[o], B = g_B2[o];
        short4 a = *(const short4*)(g_y2 + idx);
        float4 x = *(const float4*)(x0 + idx);
        float4 r;
        // z = (float)acc + x0 — bitwise identical to the value used in fused stats
        r.x = fminf(fmaxf(fmaf((float)a.x + x.x, A, B), -1.f), 1.f);
        r.y = fminf(fmaxf(fmaf((float)a.y + x.y, A, B), -1.f), 1.f);
        r.z = fminf(fmaxf(fmaf((float)a.z + x.z, A, B), -1.f), 1.f);
        r.w = fminf(fmaxf(fmaf((float)a.w + x.w, A, B), -1.f), 1.f);
        *(float4*)(out + idx) = r;
    }
    if (v == 0) out[out_size - 1] = reg0[0] + g_regbase;
}

// ---------------- launch ----------------
extern "C" void kernel_launch(void* const* d_in, const int* in_sizes, int n_in,
                              void* d_out, int out_size) {
    const float* x0   = (const float*)d_in[0];
    const float* reg0 = (const float*)d_in[1];
    const float* w1   = (const float*)d_in[2];
    const float* g1   = (const float*)d_in[3];
    const float* b1   = (const float*)d_in[4];
    const float* w2   = (const float*)d_in[5];
    const float* g2   = (const float*)d_in[6];
    const float* b2   = (const float*)d_in[7];
    float* out = (float*)d_out;

    k_init<<<1, 512>>>();                       // 0
    k_packw<<<512, 256>>>(w1, w2);              // 1
    k_pack_x<<<Nn*Hh, 256>>>(x0);               // 2
    k_conv_int<1><<<Nn*15, 256>>>(nullptr, 0);  // 3
    k_conv_bnd<1><<<Nn*8, 128>>>(nullptr, 0);   // 4
    k_coef1<<<1, Cc>>>(g1, b1);                 // 5
    k_pack2<<<Nn*Hh, 256>>>();                  // 6
    k_conv_int<2><<<Nn*15, 256>>>(x0, 1);       // 7
    k_conv_bnd<2><<<Nn*8, 128>>>(x0, 1);        // 8
    k_coef2<<<1, Cc>>>(g2, b2);                 // 9
    k_final<<<(NCHW/4 + 255) / 256, 256>>>(out, reg0, x0, out_size);  // 10
}

// round 8
// speedup vs baseline: 1.0880x; 1.0880x over previous
#include <cuda_runtime.h>
#include <cstdint>

#define Nn 32
#define Cc 256
#define Hh 32
#define Ww 32
#define HW (Hh*Ww)
#define NCHW (Nn*Cc*Hh*Ww)
#define NPIX (Nn*Hh*Ww)
#define NCHUNK 36

// ---------------- scratch (device globals; no allocation) ----------------
__device__ uint32_t           g_xbits[NPIX*8];        // channel-packed sign bits of current conv input
__device__ uint32_t           g_wchan[2][Cc*72];      // channel-packed weights [o][j=0..8][k=0..7]
__device__ unsigned long long g_wrT[2][NCHUNK*Cc];    // r-packed weights, transposed [chunk][o]
__device__ int16_t            g_y1[NCHW];             // conv1 output (clipped int)
__device__ int16_t            g_y2[NCHW];             // conv2 output (clipped int, pre-residual)
__device__ int                g_s1[Cc], g_q1[Cc];     // conv1 channel stats (exact int32)
__device__ float              g_A1[Cc], g_B1[Cc];     // bn1 sign-test coefs
__device__ double             g_S2[Cc], g_Q2[Cc];     // bn2 channel stats
__device__ float              g_A2[Cc], g_B2[Cc];
__device__ unsigned long long g_vmask[9*NCHUNK];      // per boundary-class valid-bit mask per chunk
__device__ int                g_V[9*NCHUNK];          // valid counts
__device__ float              g_regbase;              // 3*G/1024

// ---------------- init: geometric tables + stat reset + regularizer ----------------
__global__ void k_init() {
    int t = threadIdx.x;
    if (t < 9*NCHUNK) {
        int cls = t / NCHUNK, i = t % NCHUNK;
        int ht = cls / 3, wt = cls % 3;
        int r = 64*i, c = r/9, j = r - 9*c;
        unsigned long long m = 0;
        for (int b = 0; b < 64; b++) {
            int kh = j/3, kw = j - 3*kh;
            bool inval = (ht==0 && kh==0) || (ht==2 && kh==2) ||
                         (wt==0 && kw==0) || (wt==2 && kw==2);
            if (!inval) m |= 1ull << b;
            if (++j == 9) { j = 0; c++; }
        }
        g_vmask[t] = m;
        g_V[t] = __popcll(m);
    }
    if (t < Cc) { g_s1[t] = 0; g_q1[t] = 0; g_S2[t] = 0.0; g_Q2[t] = 0.0; }
    __syncthreads();
    if (t == 0) {
        // reg = r1 + 2*r2 = 3 * sum_{chunks,pixels} parity / (H*W); parity is geometric
        long long G = 0;
        int npix[3] = {1, 30, 1};
        for (int cls = 0; cls < 9; cls++) {
            long long cnt = (long long)npix[cls/3] * npix[cls%3];
            for (int i = 0; i < NCHUNK; i++)
                G += cnt * (long long)(g_V[cls*NCHUNK + i] & 1);
        }
        g_regbase = 3.0f * (float)G / (float)HW;
    }
}

// ---------------- weight packing: both layouts, both convs, one kernel ----------------
__global__ void k_packw(const float* __restrict__ w1, const float* __restrict__ w2) {
    int o    = blockIdx.x & 255;
    int slot = blockIdx.x >> 8;
    const float* w = slot ? w2 : w1;
    int warp = threadIdx.x >> 5, lane = threadIdx.x & 31;

    // r-packed transposed: bit b of word [i][o] = sign(w[o, r=64i+b])
    for (int i = warp; i < NCHUNK; i += 8) {
        unsigned lo = __ballot_sync(0xffffffffu, w[o*2304 + 64*i + lane]      >= 0.f);
        unsigned hi = __ballot_sync(0xffffffffu, w[o*2304 + 64*i + 32 + lane] >= 0.f);
        if (lane == 0)
            g_wrT[slot][i*Cc + o] = (unsigned long long)lo | ((unsigned long long)hi << 32);
    }

    // channel-packed: word [o][j][c>>5], bit (c&31)
    int c = threadIdx.x;
    float v[9];
    #pragma unroll
    for (int j = 0; j < 9; j++) v[j] = w[o*2304 + c*9 + j];
    #pragma unroll
    for (int j = 0; j < 9; j++) {
        unsigned b = __ballot_sync(0xffffffffu, v[j] >= 0.f);
        if (lane == 0) g_wchan[slot][o*72 + j*8 + (c >> 5)] = b;
    }
}

// ---------------- input packing ----------------
__global__ void k_pack_x(const float* __restrict__ x) {
    int n = blockIdx.x >> 5, h = blockIdx.x & 31;
    int w = threadIdx.x & 31, k = threadIdx.x >> 5;
    const float* base = x + ((size_t)(n*Cc + k*32) * Hh + h) * Ww + w;
    uint32_t word = 0;
    #pragma unroll 8
    for (int cc = 0; cc < 32; cc++)
        if (base[(size_t)cc * HW] >= 0.f) word |= 1u << cc;
    g_xbits[((n*Hh + h)*Ww + w)*8 + k] = word;
}

// pack sign of bn1(hardtanh preserves sign): bit = (y*A1[c] + B1[c] >= 0)
__global__ void k_pack2() {
    int n = blockIdx.x >> 5, h = blockIdx.x & 31;
    int w = threadIdx.x & 31, k = threadIdx.x >> 5;
    const int16_t* base = g_y1 + ((size_t)(n*Cc + k*32) * Hh + h) * Ww + w;
    uint32_t word = 0;
    #pragma unroll 8
    for (int cc = 0; cc < 32; cc++) {
        int c = k*32 + cc;
        float y = (float)base[(size_t)cc * HW];
        if (fmaf(y, g_A1[c], g_B1[c]) >= 0.f) word |= 1u << cc;
    }
    g_xbits[((n*Hh + h)*Ww + w)*8 + k] = word;
}

// ---------------- CSA helpers: single-LOP3 xor3 / majority ----------------
__device__ __forceinline__ uint32_t lop3_x3(uint32_t a, uint32_t b, uint32_t c) {
    uint32_t r;
    asm("lop3.b32 %0, %1, %2, %3, 0x96;" : "=r"(r) : "r"(a), "r"(b), "r"(c));
    return r;   // a ^ b ^ c
}
__device__ __forceinline__ uint32_t lop3_maj(uint32_t a, uint32_t b, uint32_t c) {
    uint32_t r;
    asm("lop3.b32 %0, %1, %2, %3, 0xE8;" : "=r"(r) : "r"(a), "r"(b), "r"(c));
    return r;   // majority(a,b,c)
}

// popcount of 8 XNOR-diff words via 4 full-adders: 4 POPC instead of 8.
// Sum popc(v0..v7) = popc(s3) + popc(v7) + 2*popc(s4) + 4*popc(c4)   (exact)
__device__ __forceinline__ int tap_count(uint4 xa, uint4 xb, uint4 wa, uint4 wb) {
    uint32_t v0 = xa.x ^ wa.x, v1 = xa.y ^ wa.y, v2 = xa.z ^ wa.z, v3 = xa.w ^ wa.w;
    uint32_t v4 = xb.x ^ wb.x, v5 = xb.y ^ wb.y, v6 = xb.z ^ wb.z, v7 = xb.w ^ wb.w;
    uint32_t sA = lop3_x3(v0, v1, v2), cA = lop3_maj(v0, v1, v2);
    uint32_t sB = lop3_x3(v3, v4, v5), cB = lop3_maj(v3, v4, v5);
    uint32_t s3 = lop3_x3(sA, sB, v6), c3 = lop3_maj(sA, sB, v6);
    uint32_t s4 = lop3_x3(cA, cB, c3), c4 = lop3_maj(cA, cB, c3);
    return __popc(s3) + __popc(v7) + 2*__popc(s4) + 4*__popc(c4);
}

// ---------------- interior conv: block = (n, 5-pair row group, 64-o quarter) ----------------
// weights loaded to smem ONCE per block, reused across 5 row-pairs; single-wave grid (384 blocks)
// quantization is an exact no-op for interior pixels (psum always even, |psum|<=64)
template<int MODE>   // 1: write y1 int16 + int stats; 2: write y2 int16 + float stats on z=acc+res
__global__ void __launch_bounds__(256, 3) k_conv_int(const float* __restrict__ x0res, int slot) {
    int b   = blockIdx.x;            // 384 = 32 n * 3 grp * 4 oq
    int oq  = b & 3;
    int grp = (b >> 2) % 3;
    int n   = b / 12;
    __shared__ __align__(16) uint32_t sx[4][Ww][8];      // 4 KB
    __shared__ __align__(16) uint32_t sw[64*72];         // 18 KB: this block's 64-o weights
    int t = threadIdx.x;

    // load this block's weights once: 64*72 words = 1152 uint4
    const uint4* gsrc = (const uint4*)(g_wchan[slot] + oq*64*72);
    #pragma unroll
    for (int i = 0; i < 1152/256; i++) ((uint4*)sw)[t + i*256] = gsrc[t + i*256];
    if (t < 128) ((uint4*)sw)[1024 + t] = gsrc[1024 + t];

    int w = t & 31, warp = t >> 5;
    int wl = (w > 0) ? w-1 : 0;
    int wr = (w < 31) ? w+1 : 31;
    const int wcol[3] = {wl, w, wr};
    bool valid = (w >= 1 && w <= 30);
    int ob = warp*8;   // this warp's 8 o's within the quarter

    for (int pp = 0; pp < 5; pp++) {
        int h0 = 1 + 2*(grp*5 + pp);                 // rows h0, h0+1; halo h0-1..h0+2
        __syncthreads();   // protect sx reuse (first iter: also orders sw load before use)
        ((uint4*)sx)[t] = ((const uint4*)(g_xbits + (size_t)(n*Hh + (h0-1)) * Ww * 8))[t];
        __syncthreads();

        size_t base0 = (((size_t)n*Cc*Hh) + h0) * Ww + w;   // + o*HW

        // packed accumulators: low 16 = row0 popc-sum, high 16 = row1 (each <= 2304, no carry)
        int s01[8];
        #pragma unroll
        for (int oo = 0; oo < 8; oo++) s01[oo] = 0;

        #pragma unroll
        for (int j = 0; j < 9; j++) {
            int rr = j / 3;
            int wc = wcol[j % 3];
            const uint32_t* xp0 = &sx[rr][wc][0];
            uint4 xa = *(const uint4*)xp0;
            uint4 xb = *(const uint4*)(xp0 + 4);
            const uint32_t* xp1 = &sx[rr+1][wc][0];
            uint4 ya = *(const uint4*)xp1;
            uint4 yb = *(const uint4*)(xp1 + 4);
            #pragma unroll
            for (int oo = 0; oo < 8; oo++) {
                const uint4* wp = (const uint4*)(&sw[(ob + oo)*72 + j*8]);
                uint4 wa = wp[0];
                uint4 wb = wp[1];
                int t0 = tap_count(xa, xb, wa, wb);
                int t1 = tap_count(ya, yb, wa, wb);
                s01[oo] += t0 + (t1 << 16);
            }
        }

        #pragma unroll
        for (int oo = 0; oo < 8; oo++) {
            int o = oq*64 + ob + oo;
            int s0 = s01[oo] & 0xFFFF;
            int s1 = s01[oo] >> 16;
            int a0 = min(max(2304 - 2*s0, -254), 254);
            int a1 = min(max(2304 - 2*s1, -254), 254);
            size_t idx = base0 + (size_t)o * HW;
            if (MODE == 1) {
                if (valid) { g_y1[idx] = (int16_t)a0; g_y1[idx + Ww] = (int16_t)a1; }
                int vs = valid ? (a0 + a1) : 0;
                int vq = valid ? (a0*a0 + a1*a1) : 0;
                vs = __reduce_add_sync(0xffffffffu, vs);
                vq = __reduce_add_sync(0xffffffffu, vq);
                if (w == 0) { atomicAdd(&g_s1[o], vs); atomicAdd(&g_q1[o], vq); }
            } else {
                float z0 = 0.f, z1 = 0.f;
                if (valid) {
                    z0 = (float)a0 + x0res[idx];
                    z1 = (float)a1 + x0res[idx + Ww];
                    g_y2[idx] = (int16_t)a0; g_y2[idx + Ww] = (int16_t)a1;
                }
                float fs = z0 + z1, fq = z0*z0 + z1*z1;
                #pragma unroll
                for (int d = 16; d; d >>= 1) {
                    fs += __shfl_xor_sync(0xffffffffu, fs, d);
                    fq += __shfl_xor_sync(0xffffffffu, fq, d);
                }
                if (w == 0) { atomicAdd(&g_S2[o], (double)fs); atomicAdd(&g_Q2[o], (double)fq); }
            }
        }
    }
}

// ---------------- boundary conv: exact chunked psum, banker's rounding, fused stats ----------------
template<int MODE>
__global__ void k_conv_bnd(const float* __restrict__ x0res, int slot) {
    int n = blockIdx.x / 124, b = blockIdx.x % 124;
    int h, w;
    if      (b < 32) { h = 0;      w = b; }
    else if (b < 64) { h = 31;     w = b - 32; }
    else if (b < 94) { w = 0;      h = b - 63; }
    else             { w = 31;     h = b - 93; }
    int ht  = (h == 0) ? 0 : ((h == 31) ? 2 : 1);
    int wt  = (w == 0) ? 0 : ((w == 31) ? 2 : 1);
    int cls = ht*3 + wt;

    __shared__ unsigned long long sxr[NCHUNK];
    __shared__ int soff[9];
    int t = threadIdx.x;
    int warp = t >> 5, lane = t & 31;
    if (t < 9) {
        int kh = t / 3, kw = t % 3;
        int hh = min(max(h + kh - 1, 0), 31);
        int ww = min(max(w + kw - 1, 0), 31);
        soff[t] = ((n*Hh + hh)*Ww + ww) * 8;
    }
    __syncthreads();
    // warp-parallel r-ordered word build via ballot (chunk i, bit b: r=64i+b, c=r/9, j=r%9)
    for (int i = warp; i < NCHUNK; i += 8) {
        int r0 = 64*i + lane;
        int c0 = r0 / 9, j0 = r0 - 9*c0;
        unsigned lo = __ballot_sync(0xffffffffu,
            (g_xbits[soff[j0] + (c0 >> 5)] >> (c0 & 31)) & 1u);
        int r1 = r0 + 32;
        int c1 = r1 / 9, j1 = r1 - 9*c1;
        unsigned hi = __ballot_sync(0xffffffffu,
            (g_xbits[soff[j1] + (c1 >> 5)] >> (c1 & 31)) & 1u);
        if (lane == 0)
            sxr[i] = (unsigned long long)lo | ((unsigned long long)hi << 32);
    }
    __syncthreads();

    int o = t;   // 256 threads = 256 output channels
    int acc = 0;
    #pragma unroll 4
    for (int i = 0; i < NCHUNK; i++) {
        unsigned long long X = (sxr[i] ^ g_wrT[slot][i*Cc + o]) & g_vmask[cls*NCHUNK + i];
        int psum = g_V[cls*NCHUNK + i] - 2*__popcll(X);
        int rmod = psum & 3;                   // two's-complement mod 4
        psum += (rmod == 3) - (rmod == 1);     // round-half-to-even of psum/2, *2
        acc += psum;
    }
    acc = min(max(acc, -254), 254);
    size_t idx = ((size_t)(n*Cc + o) * Hh + h) * Ww + w;
    if (MODE == 1) {
        g_y1[idx] = (int16_t)acc;
        atomicAdd(&g_s1[o], acc);
        atomicAdd(&g_q1[o], acc*acc);
    } else {
        float z = (float)acc + x0res[idx];
        g_y2[idx] = (int16_t)acc;
        atomicAdd(&g_S2[o], (double)z);
        atomicAdd(&g_Q2[o], (double)(z*z));
    }
}

// ---------------- BN coefficient kernels ----------------
__global__ void k_coef1(const float* __restrict__ gamma, const float* __restrict__ beta) {
    int o = threadIdx.x;
    double m   = (double)g_s1[o] / (double)(Nn*HW);
    double var = (double)g_q1[o] / (double)(Nn*HW) - m*m;
    float inv  = (float)(1.0 / sqrt(var + 1e-5));
    float A = gamma[o] * inv;
    g_A1[o] = A;
    g_B1[o] = beta[o] - (float)m * A;
}

__global__ void k_coef2(const float* __restrict__ gamma, const float* __restrict__ beta) {
    int o = threadIdx.x;
    double m   = g_S2[o] / (double)(Nn*HW);
    double var = g_Q2[o] / (double)(Nn*HW) - m*m;
    float inv  = (float)(1.0 / sqrt(var + 1e-5));
    float A = gamma[o] * inv;
    g_A2[o] = A;
    g_B2[o] = beta[o] - (float)m * A;
}

// ---------------- finalize: z = acc2 + residual, bn2 + hardtanh, regularizer scalar ----------------
__global__ void k_final(float* __restrict__ out, const float* __restrict__ reg0,
                        const float* __restrict__ x0, int out_size) {
    size_t v = (size_t)blockIdx.x * 256 + threadIdx.x;   // 4-element group index
    size_t idx = v * 4;
    if (idx < (size_t)NCHW) {
        int o = (int)((idx >> 10) & 255);
        float A = g_A2[o], B = g_B2[o];
        short4 a = *(const short4*)(g_y2 + idx);
        float4 x = *(const float4*)(x0 + idx);
        float4 r;
        // z = (float)acc + x0 — bitwise identical to the value used in fused stats
        r.x = fminf(fmaxf(fmaf((float)a.x + x.x, A, B), -1.f), 1.f);
        r.y = fminf(fmaxf(fmaf((float)a.y + x.y, A, B), -1.f), 1.f);
        r.z = fminf(fmaxf(fmaf((float)a.z + x.z, A, B), -1.f), 1.f);
        r.w = fminf(fmaxf(fmaf((float)a.w + x.w, A, B), -1.f), 1.f);
        *(float4*)(out + idx) = r;
    }
    if (v == 0) out[out_size - 1] = reg0[0] + g_regbase;
}

// ---------------- launch ----------------
extern "C" void kernel_launch(void* const* d_in, const int* in_sizes, int n_in,
                              void* d_out, int out_size) {
    const float* x0   = (const float*)d_in[0];
    const float* reg0 = (const float*)d_in[1];
    const float* w1   = (const float*)d_in[2];
    const float* g1   = (const float*)d_in[3];
    const float* b1   = (const float*)d_in[4];
    const float* w2   = (const float*)d_in[5];
    const float* g2   = (const float*)d_in[6];
    const float* b2   = (const float*)d_in[7];
    float* out = (float*)d_out;

    k_init<<<1, 512>>>();                       // 0
    k_packw<<<512, 256>>>(w1, w2);              // 1
    k_pack_x<<<Nn*Hh, 256>>>(x0);               // 2
    k_conv_int<1><<<384, 256>>>(nullptr, 0);    // 3
    k_conv_bnd<1><<<Nn*124, 256>>>(nullptr, 0); // 4
    k_coef1<<<1, Cc>>>(g1, b1);                 // 5
    k_pack2<<<Nn*Hh, 256>>>();                  // 6
    k_conv_int<2><<<384, 256>>>(x0, 1);         // 7
    k_conv_bnd<2><<<Nn*124, 256>>>(x0, 1);      // 8
    k_coef2<<<1, Cc>>>(g2, b2);                 // 9
    k_final<<<(NCHW/4 + 255) / 256, 256>>>(out, reg0, x0, out_size);  // 10
}

// round 10
// speedup vs baseline: 1.1628x; 1.0687x over previous
#include <cuda_runtime.h>
#include <cstdint>

#define Nn 32
#define Cc 256
#define Hh 32
#define Ww 32
#define HW (Hh*Ww)
#define NCHW (Nn*Cc*Hh*Ww)
#define NPIX (Nn*Hh*Ww)
#define NCHUNK 36
#define NUNITS (4*Nn*15)   // (oq, n, pair) work units = 1920

// ---------------- scratch (device globals; no allocation) ----------------
__device__ uint32_t           g_xbits[NPIX*8];        // channel-packed sign bits of current conv input
__device__ uint32_t           g_wchan[2][Cc*72];      // channel-packed weights [o][j=0..8][k=0..7]
__device__ unsigned long long g_wrT[2][NCHUNK*Cc];    // r-packed weights, transposed [chunk][o]
__device__ int8_t             g_y1b[NCHW];            // conv1 output, acc>>1 (acc provably even)
__device__ int8_t             g_y2b[NCHW];            // conv2 output, acc>>1 (pre-residual)
__device__ int                g_s1[Cc], g_q1[Cc];     // conv1 channel stats (exact int32)
__device__ float              g_A1[Cc], g_B1[Cc];     // bn1 sign-test coefs
__device__ double             g_S2[Cc], g_Q2[Cc];     // bn2 channel stats
__device__ float              g_A2[Cc], g_B2[Cc];
__device__ unsigned long long g_vmask[9*NCHUNK];      // per boundary-class valid-bit mask per chunk
__device__ int                g_V[9*NCHUNK];          // valid counts
__device__ int                g_work[2];              // persistent-conv work counters
__device__ float              g_regbase;              // 3*G/1024

// ---------------- init: geometric tables + stat/counter reset + regularizer ----------------
__global__ void k_init() {
    int t = threadIdx.x;
    if (t < 9*NCHUNK) {
        int cls = t / NCHUNK, i = t % NCHUNK;
        int ht = cls / 3, wt = cls % 3;
        int r = 64*i, c = r/9, j = r - 9*c;
        unsigned long long m = 0;
        for (int b = 0; b < 64; b++) {
            int kh = j/3, kw = j - 3*kh;
            bool inval = (ht==0 && kh==0) || (ht==2 && kh==2) ||
                         (wt==0 && kw==0) || (wt==2 && kw==2);
            if (!inval) m |= 1ull << b;
            if (++j == 9) { j = 0; c++; }
        }
        g_vmask[t] = m;
        g_V[t] = __popcll(m);
    }
    if (t < Cc) { g_s1[t] = 0; g_q1[t] = 0; g_S2[t] = 0.0; g_Q2[t] = 0.0; }
    if (t < 2)  g_work[t] = 0;
    __syncthreads();
    if (t == 0) {
        // reg = r1 + 2*r2 = 3 * sum_{chunks,pixels} parity / (H*W); parity is geometric
        long long G = 0;
        int npix[3] = {1, 30, 1};
        for (int cls = 0; cls < 9; cls++) {
            long long cnt = (long long)npix[cls/3] * npix[cls%3];
            for (int i = 0; i < NCHUNK; i++)
                G += cnt * (long long)(g_V[cls*NCHUNK + i] & 1);
        }
        g_regbase = 3.0f * (float)G / (float)HW;
    }
}

// ---------------- weight packing: both layouts, both convs, one kernel ----------------
__global__ void k_packw(const float* __restrict__ w1, const float* __restrict__ w2) {
    int o    = blockIdx.x & 255;
    int slot = blockIdx.x >> 8;
    const float* w = slot ? w2 : w1;
    int warp = threadIdx.x >> 5, lane = threadIdx.x & 31;

    // r-packed transposed: bit b of word [i][o] = sign(w[o, r=64i+b])
    for (int i = warp; i < NCHUNK; i += 8) {
        unsigned lo = __ballot_sync(0xffffffffu, w[o*2304 + 64*i + lane]      >= 0.f);
        unsigned hi = __ballot_sync(0xffffffffu, w[o*2304 + 64*i + 32 + lane] >= 0.f);
        if (lane == 0)
            g_wrT[slot][i*Cc + o] = (unsigned long long)lo | ((unsigned long long)hi << 32);
    }

    // channel-packed: word [o][j][c>>5], bit (c&31)
    int c = threadIdx.x;
    float v[9];
    #pragma unroll
    for (int j = 0; j < 9; j++) v[j] = w[o*2304 + c*9 + j];
    #pragma unroll
    for (int j = 0; j < 9; j++) {
        unsigned b = __ballot_sync(0xffffffffu, v[j] >= 0.f);
        if (lane == 0) g_wchan[slot][o*72 + j*8 + (c >> 5)] = b;
    }
}

// ---------------- input packing ----------------
__global__ void k_pack_x(const float* __restrict__ x) {
    int n = blockIdx.x >> 5, h = blockIdx.x & 31;
    int w = threadIdx.x & 31, k = threadIdx.x >> 5;
    const float* base = x + ((size_t)(n*Cc + k*32) * Hh + h) * Ww + w;
    uint32_t word = 0;
    #pragma unroll 8
    for (int cc = 0; cc < 32; cc++)
        if (base[(size_t)cc * HW] >= 0.f) word |= 1u << cc;
    g_xbits[((n*Hh + h)*Ww + w)*8 + k] = word;
}

// pack sign of bn1(hardtanh preserves sign): bit = (y*A1[c] + B1[c] >= 0), y = 2*stored
__global__ void k_pack2() {
    int n = blockIdx.x >> 5, h = blockIdx.x & 31;
    int w = threadIdx.x & 31, k = threadIdx.x >> 5;
    const int8_t* base = g_y1b + ((size_t)(n*Cc + k*32) * Hh + h) * Ww + w;
    uint32_t word = 0;
    #pragma unroll 8
    for (int cc = 0; cc < 32; cc++) {
        int c = k*32 + cc;
        float y = (float)(2 * (int)base[(size_t)cc * HW]);
        if (fmaf(y, g_A1[c], g_B1[c]) >= 0.f) word |= 1u << cc;
    }
    g_xbits[((n*Hh + h)*Ww + w)*8 + k] = word;
}

// ---------------- CSA helpers: single-LOP3 xor3 / majority ----------------
__device__ __forceinline__ uint32_t lop3_x3(uint32_t a, uint32_t b, uint32_t c) {
    uint32_t r;
    asm("lop3.b32 %0, %1, %2, %3, 0x96;" : "=r"(r) : "r"(a), "r"(b), "r"(c));
    return r;   // a ^ b ^ c
}
__device__ __forceinline__ uint32_t lop3_maj(uint32_t a, uint32_t b, uint32_t c) {
    uint32_t r;
    asm("lop3.b32 %0, %1, %2, %3, 0xE8;" : "=r"(r) : "r"(a), "r"(b), "r"(c));
    return r;   // majority(a,b,c)
}

// popcount of 8 XNOR-diff words via 4 full-adders: 4 POPC instead of 8.
// Sum popc(v0..v7) = popc(s3) + popc(v7) + 2*popc(s4) + 4*popc(c4)   (exact)
__device__ __forceinline__ int tap_count(uint4 xa, uint4 xb, uint4 wa, uint4 wb) {
    uint32_t v0 = xa.x ^ wa.x, v1 = xa.y ^ wa.y, v2 = xa.z ^ wa.z, v3 = xa.w ^ wa.w;
    uint32_t v4 = xb.x ^ wb.x, v5 = xb.y ^ wb.y, v6 = xb.z ^ wb.z, v7 = xb.w ^ wb.w;
    uint32_t sA = lop3_x3(v0, v1, v2), cA = lop3_maj(v0, v1, v2);
    uint32_t sB = lop3_x3(v3, v4, v5), cB = lop3_maj(v3, v4, v5);
    uint32_t s3 = lop3_x3(sA, sB, v6), c3 = lop3_maj(sA, sB, v6);
    uint32_t s4 = lop3_x3(cA, cB, c3), c4 = lop3_maj(cA, cB, c3);
    return __popc(s3) + __popc(v7) + 2*__popc(s4) + 4*__popc(c4);
}

// ---------------- interior conv: persistent blocks + work-stealing over (oq, n, pair) ----------------
// grid = 296 = 2 blocks/SM uniform; units oq-major so smem weights are reused across units.
// quantization is an exact no-op for interior pixels (psum always even, |psum|<=64)
template<int MODE>   // 1: write y1b + int stats; 2: write y2b + float stats on z=acc+res
__global__ void __launch_bounds__(256, 2) k_conv_int(const float* __restrict__ x0res, int slot) {
    __shared__ __align__(16) uint32_t sx[4][Ww][8];      // 4 KB
    __shared__ __align__(16) uint32_t sw[64*72];         // 18 KB: current oq's 64-o weights
    __shared__ int s_u;
    int t = threadIdx.x;
    int w = t & 31, warp = t >> 5;
    int wl = (w > 0) ? w-1 : 0;
    int wr = (w < 31) ? w+1 : 31;
    const int wcol[3] = {wl, w, wr};
    bool valid = (w >= 1 && w <= 30);
    int ob = warp*8;   // this warp's 8 o's within the oq quarter
    int cur_oq = -1;

    for (;;) {
        if (t == 0) s_u = atomicAdd(&g_work[MODE-1], 1);
        __syncthreads();            // publish s_u; all threads done with prior sx/sw
        int u = s_u;
        if (u >= NUNITS) break;
        int oq   = u / (NUNITS/4);
        int rem  = u - oq*(NUNITS/4);
        int n    = rem / 15, pair = rem - n*15;

        if (oq != cur_oq) {         // (re)load weights for this quarter: 1152 uint4
            const uint4* gsrc = (const uint4*)(g_wchan[slot] + oq*64*72);
            #pragma unroll
            for (int i = 0; i < 1152/256; i++) ((uint4*)sw)[t + i*256] = gsrc[t + i*256];
            if (t < 128) ((uint4*)sw)[1024 + t] = gsrc[1024 + t];
            cur_oq = oq;
        }
        int h0 = 1 + 2*pair;        // rows h0, h0+1; halo rows h0-1..h0+2
        ((uint4*)sx)[t] = ((const uint4*)(g_xbits + (size_t)(n*Hh + (h0-1)) * Ww * 8))[t];
        __syncthreads();

        size_t base0 = (((size_t)n*Cc*Hh) + h0) * Ww + w;   // + o*HW

        // packed accumulators: low 16 = row0 popc-sum, high 16 = row1 (each <= 2304, no carry)
        int s01[8];
        #pragma unroll
        for (int oo = 0; oo < 8; oo++) s01[oo] = 0;

        #pragma unroll
        for (int j = 0; j < 9; j++) {
            int rr = j / 3;
            int wc = wcol[j % 3];
            const uint32_t* xp0 = &sx[rr][wc][0];
            uint4 xa = *(const uint4*)xp0;
            uint4 xb = *(const uint4*)(xp0 + 4);
            const uint32_t* xp1 = &sx[rr+1][wc][0];
            uint4 ya = *(const uint4*)xp1;
            uint4 yb = *(const uint4*)(xp1 + 4);
            #pragma unroll
            for (int oo = 0; oo < 8; oo++) {
                const uint4* wp = (const uint4*)(&sw[(ob + oo)*72 + j*8]);
                uint4 wa = wp[0];
                uint4 wb = wp[1];
                int t0 = tap_count(xa, xb, wa, wb);
                int t1 = tap_count(ya, yb, wa, wb);
                s01[oo] += t0 + (t1 << 16);
            }
        }

        #pragma unroll
        for (int oo = 0; oo < 8; oo++) {
            int o = oq*64 + ob + oo;
            int s0 = s01[oo] & 0xFFFF;
            int s1 = s01[oo] >> 16;
            int a0 = min(max(2304 - 2*s0, -254), 254);
            int a1 = min(max(2304 - 2*s1, -254), 254);
            size_t idx = base0 + (size_t)o * HW;
            if (MODE == 1) {
                if (valid) { g_y1b[idx] = (int8_t)(a0 >> 1); g_y1b[idx + Ww] = (int8_t)(a1 >> 1); }
                int vs = valid ? (a0 + a1) : 0;
                int vq = valid ? (a0*a0 + a1*a1) : 0;
                vs = __reduce_add_sync(0xffffffffu, vs);
                vq = __reduce_add_sync(0xffffffffu, vq);
                if (w == 0) { atomicAdd(&g_s1[o], vs); atomicAdd(&g_q1[o], vq); }
            } else {
                float z0 = 0.f, z1 = 0.f;
                if (valid) {
                    z0 = (float)a0 + x0res[idx];
                    z1 = (float)a1 + x0res[idx + Ww];
                    g_y2b[idx] = (int8_t)(a0 >> 1); g_y2b[idx + Ww] = (int8_t)(a1 >> 1);
                }
                float fs = z0 + z1, fq = z0*z0 + z1*z1;
                #pragma unroll
                for (int d = 16; d; d >>= 1) {
                    fs += __shfl_xor_sync(0xffffffffu, fs, d);
                    fq += __shfl_xor_sync(0xffffffffu, fq, d);
                }
                if (w == 0) { atomicAdd(&g_S2[o], (double)fs); atomicAdd(&g_Q2[o], (double)fq); }
            }
        }
    }
}

// ---------------- boundary conv: exact chunked psum, banker's rounding, fused stats ----------------
template<int MODE>
__global__ void k_conv_bnd(const float* __restrict__ x0res, int slot) {
    int n = blockIdx.x / 124, b = blockIdx.x % 124;
    int h, w;
    if      (b < 32) { h = 0;      w = b; }
    else if (b < 64) { h = 31;     w = b - 32; }
    else if (b < 94) { w = 0;      h = b - 63; }
    else             { w = 31;     h = b - 93; }
    int ht  = (h == 0) ? 0 : ((h == 31) ? 2 : 1);
    int wt  = (w == 0) ? 0 : ((w == 31) ? 2 : 1);
    int cls = ht*3 + wt;

    __shared__ unsigned long long sxr[NCHUNK];
    __shared__ int soff[9];
    int t = threadIdx.x;
    int warp = t >> 5, lane = t & 31;
    if (t < 9) {
        int kh = t / 3, kw = t % 3;
        int hh = min(max(h + kh - 1, 0), 31);
        int ww = min(max(w + kw - 1, 0), 31);
        soff[t] = ((n*Hh + hh)*Ww + ww) * 8;
    }
    __syncthreads();
    // warp-parallel r-ordered word build via ballot (chunk i, bit b: r=64i+b, c=r/9, j=r%9)
    for (int i = warp; i < NCHUNK; i += 8) {
        int r0 = 64*i + lane;
        int c0 = r0 / 9, j0 = r0 - 9*c0;
        unsigned lo = __ballot_sync(0xffffffffu,
            (g_xbits[soff[j0] + (c0 >> 5)] >> (c0 & 31)) & 1u);
        int r1 = r0 + 32;
        int c1 = r1 / 9, j1 = r1 - 9*c1;
        unsigned hi = __ballot_sync(0xffffffffu,
            (g_xbits[soff[j1] + (c1 >> 5)] >> (c1 & 31)) & 1u);
        if (lane == 0)
            sxr[i] = (unsigned long long)lo | ((unsigned long long)hi << 32);
    }
    __syncthreads();

    int o = t;   // 256 threads = 256 output channels
    int acc = 0;
    #pragma unroll 4
    for (int i = 0; i < NCHUNK; i++) {
        unsigned long long X = (sxr[i] ^ g_wrT[slot][i*Cc + o]) & g_vmask[cls*NCHUNK + i];
        int psum = g_V[cls*NCHUNK + i] - 2*__popcll(X);
        int rmod = psum & 3;                   // two's-complement mod 4
        psum += (rmod == 3) - (rmod == 1);     // round-half-to-even of psum/2, *2
        acc += psum;
    }
    acc = min(max(acc, -254), 254);
    size_t idx = ((size_t)(n*Cc + o) * Hh + h) * Ww + w;
    if (MODE == 1) {
        g_y1b[idx] = (int8_t)(acc >> 1);
        atomicAdd(&g_s1[o], acc);
        atomicAdd(&g_q1[o], acc*acc);
    } else {
        float z = (float)acc + x0res[idx];
        g_y2b[idx] = (int8_t)(acc >> 1);
        atomicAdd(&g_S2[o], (double)z);
        atomicAdd(&g_Q2[o], (double)(z*z));
    }
}

// ---------------- BN coefficient kernels ----------------
__global__ void k_coef1(const float* __restrict__ gamma, const float* __restrict__ beta) {
    int o = threadIdx.x;
    double m   = (double)g_s1[o] / (double)(Nn*HW);
    double var = (double)g_q1[o] / (double)(Nn*HW) - m*m;
    float inv  = (float)(1.0 / sqrt(var + 1e-5));
    float A = gamma[o] * inv;
    g_A1[o] = A;
    g_B1[o] = beta[o] - (float)m * A;
}

__global__ void k_coef2(const float* __restrict__ gamma, const float* __restrict__ beta) {
    int o = threadIdx.x;
    double m   = g_S2[o] / (double)(Nn*HW);
    double var = g_Q2[o] / (double)(Nn*HW) - m*m;
    float inv  = (float)(1.0 / sqrt(var + 1e-5));
    float A = gamma[o] * inv;
    g_A2[o] = A;
    g_B2[o] = beta[o] - (float)m * A;
}

// ---------------- finalize: z = 2*y2b + residual, bn2 + hardtanh, regularizer scalar ----------------
__global__ void k_final(float* __restrict__ out, const float* __restrict__ reg0,
                        const float* __restrict__ x0, int out_size) {
    size_t v = (size_t)blockIdx.x * 256 + threadIdx.x;   // 4-element group index
    size_t idx = v * 4;
    if (idx < (size_t)NCHW) {
        int o = (int)((idx >> 10) & 255);
        float A = g_A2[o], B = g_B2[o];
        char4 a = *(const char4*)(g_y2b + idx);
        float4 x = *(const float4*)(x0 + idx);
        float4 r;
        // z = (float)acc + x0 — bitwise identical to the value used in fused stats
        r.x = fminf(fmaxf(fmaf((float)(2*(int)a.x) + x.x, A, B), -1.f), 1.f);
        r.y = fminf(fmaxf(fmaf((float)(2*(int)a.y) + x.y, A, B), -1.f), 1.f);
        r.z = fminf(fmaxf(fmaf((float)(2*(int)a.z) + x.z, A, B), -1.f), 1.f);
        r.w = fminf(fmaxf(fmaf((float)(2*(int)a.w) + x.w, A, B), -1.f), 1.f);
        *(float4*)(out + idx) = r;
    }
    if (v == 0) out[out_size - 1] = reg0[0] + g_regbase;
}

// ---------------- launch ----------------
extern "C" void kernel_launch(void* const* d_in, const int* in_sizes, int n_in,
                              void* d_out, int out_size) {
    const float* x0   = (const float*)d_in[0];
    const float* reg0 = (const float*)d_in[1];
    const float* w1   = (const float*)d_in[2];
    const float* g1   = (const float*)d_in[3];
    const float* b1   = (const float*)d_in[4];
    const float* w2   = (const float*)d_in[5];
    const float* g2   = (const float*)d_in[6];
    const float* b2   = (const float*)d_in[7];
    float* out = (float*)d_out;

    k_init<<<1, 512>>>();                       // 0
    k_packw<<<512, 256>>>(w1, w2);              // 1
    k_pack_x<<<Nn*Hh, 256>>>(x0);               // 2
    k_conv_int<1><<<296, 256>>>(nullptr, 0);    // 3  persistent + work-stealing
    k_conv_bnd<1><<<Nn*124, 256>>>(nullptr, 0); // 4
    k_coef1<<<1, Cc>>>(g1, b1);                 // 5
    k_pack2<<<Nn*Hh, 256>>>();                  // 6
    k_conv_int<2><<<296, 256>>>(x0, 1);         // 7
    k_conv_bnd<2><<<Nn*124, 256>>>(x0, 1);      // 8
    k_coef2<<<1, Cc>>>(g2, b2);                 // 9
    k_final<<<(NCHW/4 + 255) / 256, 256>>>(out, reg0, x0, out_size);  // 10
}

// round 14
// speedup vs baseline: 1.2358x; 1.0628x over previous
#include <cuda_runtime.h>
#include <cstdint>

#define Nn 32
#define Cc 256
#define Hh 32
#define Ww 32
#define HW (Hh*Ww)
#define NCHW (Nn*Cc*Hh*Ww)
#define NPIX (Nn*Hh*Ww)
#define NCHUNK 36
#define NUNITS (4*Nn*15)   // (oq, n, pair) work units = 1920

// ---------------- scratch (device globals; no allocation) ----------------
__device__ uint32_t           g_xbits[NPIX*8];        // channel-packed sign bits of current conv input
__device__ uint32_t           g_wchan[2][Cc*72];      // channel-packed weights [o][j=0..8][k=0..7]
__device__ unsigned long long g_wrT[2][NCHUNK*Cc];    // r-packed weights, transposed [chunk][o]
__device__ int8_t             g_y1b[NCHW];            // conv1 output, acc>>1 (acc provably even)
__device__ int8_t             g_y2b[NCHW];            // conv2 output, acc>>1 (pre-residual)
__device__ int                g_s1[Cc], g_q1[Cc];     // conv1 channel stats (exact int32)
__device__ float              g_A1[Cc], g_B1[Cc];     // bn1 sign-test coefs
__device__ double             g_S2[Cc], g_Q2[Cc];     // bn2 channel stats
__device__ float              g_A2[Cc], g_B2[Cc];
__device__ unsigned long long g_vmask[9*NCHUNK];      // per boundary-class valid-bit mask per chunk
__device__ int                g_V[9*NCHUNK];          // valid counts
__device__ int                g_SV[9], g_NO[9];       // per-class: sum V, count of odd-V chunks
__device__ int                g_work[2];              // persistent-conv work counters
__device__ float              g_regbase;              // 3*G/1024

// ---------------- init: geometric tables + stat/counter reset + regularizer ----------------
__global__ void k_init() {
    int t = threadIdx.x;
    if (t < 9*NCHUNK) {
        int cls = t / NCHUNK, i = t % NCHUNK;
        int ht = cls / 3, wt = cls % 3;
        int r = 64*i, c = r/9, j = r - 9*c;
        unsigned long long m = 0;
        for (int b = 0; b < 64; b++) {
            int kh = j/3, kw = j - 3*kh;
            bool inval = (ht==0 && kh==0) || (ht==2 && kh==2) ||
                         (wt==0 && kw==0) || (wt==2 && kw==2);
            if (!inval) m |= 1ull << b;
            if (++j == 9) { j = 0; c++; }
        }
        g_vmask[t] = m;
        g_V[t] = __popcll(m);
    }
    if (t < Cc) { g_s1[t] = 0; g_q1[t] = 0; g_S2[t] = 0.0; g_Q2[t] = 0.0; }
    if (t < 2)  g_work[t] = 0;
    __syncthreads();
    if (t < 9) {
        int sv = 0, no = 0;
        for (int i = 0; i < NCHUNK; i++) { int V = g_V[t*NCHUNK + i]; sv += V; no += V & 1; }
        g_SV[t] = sv; g_NO[t] = no;
    }
    if (t == 0) {
        // reg = r1 + 2*r2 = 3 * sum_{chunks,pixels} parity / (H*W); parity is geometric
        long long G = 0;
        int npix[3] = {1, 30, 1};
        for (int cls = 0; cls < 9; cls++) {
            long long cnt = (long long)npix[cls/3] * npix[cls%3];
            for (int i = 0; i < NCHUNK; i++)
                G += cnt * (long long)(g_V[cls*NCHUNK + i] & 1);
        }
        g_regbase = 3.0f * (float)G / (float)HW;
    }
}

// ---------------- weight packing: both layouts, both convs, one kernel ----------------
__global__ void k_packw(const float* __restrict__ w1, const float* __restrict__ w2) {
    int o    = blockIdx.x & 255;
    int slot = blockIdx.x >> 8;
    const float* w = slot ? w2 : w1;
    int warp = threadIdx.x >> 5, lane = threadIdx.x & 31;

    // r-packed transposed: bit b of word [i][o] = sign(w[o, r=64i+b])
    for (int i = warp; i < NCHUNK; i += 8) {
        unsigned lo = __ballot_sync(0xffffffffu, w[o*2304 + 64*i + lane]      >= 0.f);
        unsigned hi = __ballot_sync(0xffffffffu, w[o*2304 + 64*i + 32 + lane] >= 0.f);
        if (lane == 0)
            g_wrT[slot][i*Cc + o] = (unsigned long long)lo | ((unsigned long long)hi << 32);
    }

    // channel-packed: word [o][j][c>>5], bit (c&31)
    int c = threadIdx.x;
    float v[9];
    #pragma unroll
    for (int j = 0; j < 9; j++) v[j] = w[o*2304 + c*9 + j];
    #pragma unroll
    for (int j = 0; j < 9; j++) {
        unsigned b = __ballot_sync(0xffffffffu, v[j] >= 0.f);
        if (lane == 0) g_wchan[slot][o*72 + j*8 + (c >> 5)] = b;
    }
}

// ---------------- input packing ----------------
__global__ void k_pack_x(const float* __restrict__ x) {
    int n = blockIdx.x >> 5, h = blockIdx.x & 31;
    int w = threadIdx.x & 31, k = threadIdx.x >> 5;
    const float* base = x + ((size_t)(n*Cc + k*32) * Hh + h) * Ww + w;
    uint32_t word = 0;
    #pragma unroll 8
    for (int cc = 0; cc < 32; cc++)
        if (base[(size_t)cc * HW] >= 0.f) word |= 1u << cc;
    g_xbits[((n*Hh + h)*Ww + w)*8 + k] = word;
}

// pack sign of bn1(hardtanh preserves sign): bit = (y*A1[c] + B1[c] >= 0), y = 2*stored
__global__ void k_pack2() {
    int n = blockIdx.x >> 5, h = blockIdx.x & 31;
    int w = threadIdx.x & 31, k = threadIdx.x >> 5;
    const int8_t* base = g_y1b + ((size_t)(n*Cc + k*32) * Hh + h) * Ww + w;
    uint32_t word = 0;
    #pragma unroll 8
    for (int cc = 0; cc < 32; cc++) {
        int c = k*32 + cc;
        float y = (float)(2 * (int)base[(size_t)cc * HW]);
        if (fmaf(y, g_A1[c], g_B1[c]) >= 0.f) word |= 1u << cc;
    }
    g_xbits[((n*Hh + h)*Ww + w)*8 + k] = word;
}

// ---------------- CSA helpers: single-LOP3 xor3 / majority ----------------
__device__ __forceinline__ uint32_t lop3_x3(uint32_t a, uint32_t b, uint32_t c) {
    uint32_t r;
    asm("lop3.b32 %0, %1, %2, %3, 0x96;" : "=r"(r) : "r"(a), "r"(b), "r"(c));
    return r;   // a ^ b ^ c
}
__device__ __forceinline__ uint32_t lop3_maj(uint32_t a, uint32_t b, uint32_t c) {
    uint32_t r;
    asm("lop3.b32 %0, %1, %2, %3, 0xE8;" : "=r"(r) : "r"(a), "r"(b), "r"(c));
    return r;   // majority(a,b,c)
}

// popcount of 8 XNOR-diff words via 4 full-adders: 4 POPC instead of 8.
// Sum popc(v0..v7) = popc(s3) + popc(v7) + 2*popc(s4) + 4*popc(c4)   (exact)
__device__ __forceinline__ int tap_count(uint4 xa, uint4 xb, uint4 wa, uint4 wb) {
    uint32_t v0 = xa.x ^ wa.x, v1 = xa.y ^ wa.y, v2 = xa.z ^ wa.z, v3 = xa.w ^ wa.w;
    uint32_t v4 = xb.x ^ wb.x, v5 = xb.y ^ wb.y, v6 = xb.z ^ wb.z, v7 = xb.w ^ wb.w;
    uint32_t sA = lop3_x3(v0, v1, v2), cA = lop3_maj(v0, v1, v2);
    uint32_t sB = lop3_x3(v3, v4, v5), cB = lop3_maj(v3, v4, v5);
    uint32_t s3 = lop3_x3(sA, sB, v6), c3 = lop3_maj(sA, sB, v6);
    uint32_t s4 = lop3_x3(cA, cB, c3), c4 = lop3_maj(cA, cB, c3);
    return __popc(s3) + __popc(v7) + 2*__popc(s4) + 4*__popc(c4);
}

// ---------------- interior conv: persistent blocks + work-stealing over (oq, n, pair) ----------------
// grid = 296 = 2 blocks/SM uniform; units oq-major so smem weights are reused across units.
// quantization is an exact no-op for interior pixels (psum always even, |psum|<=64)
template<int MODE>   // 1: write y1b + int stats; 2: write y2b + float stats on z=acc+res
__global__ void __launch_bounds__(256, 2) k_conv_int(const float* __restrict__ x0res, int slot) {
    __shared__ __align__(16) uint32_t sx[4][Ww][8];      // 4 KB
    __shared__ __align__(16) uint32_t sw[64*72];         // 18 KB: current oq's 64-o weights
    __shared__ int s_u;
    int t = threadIdx.x;
    int w = t & 31, warp = t >> 5;
    int wl = (w > 0) ? w-1 : 0;
    int wr = (w < 31) ? w+1 : 31;
    const int wcol[3] = {wl, w, wr};
    bool valid = (w >= 1 && w <= 30);
    int ob = warp*8;   // this warp's 8 o's within the oq quarter
    int cur_oq = -1;

    for (;;) {
        if (t == 0) s_u = atomicAdd(&g_work[MODE-1], 1);
        __syncthreads();            // publish s_u; all threads done with prior sx/sw
        int u = s_u;
        if (u >= NUNITS) break;
        int oq   = u / (NUNITS/4);
        int rem  = u - oq*(NUNITS/4);
        int n    = rem / 15, pair = rem - n*15;

        if (oq != cur_oq) {         // (re)load weights for this quarter: 1152 uint4
            const uint4* gsrc = (const uint4*)(g_wchan[slot] + oq*64*72);
            #pragma unroll
            for (int i = 0; i < 1152/256; i++) ((uint4*)sw)[t + i*256] = gsrc[t + i*256];
            if (t < 128) ((uint4*)sw)[1024 + t] = gsrc[1024 + t];
            cur_oq = oq;
        }
        int h0 = 1 + 2*pair;        // rows h0, h0+1; halo rows h0-1..h0+2
        ((uint4*)sx)[t] = ((const uint4*)(g_xbits + (size_t)(n*Hh + (h0-1)) * Ww * 8))[t];
        __syncthreads();

        size_t base0 = (((size_t)n*Cc*Hh) + h0) * Ww + w;   // + o*HW

        // packed accumulators: low 16 = row0 popc-sum, high 16 = row1 (each <= 2304, no carry)
        int s01[8];
        #pragma unroll
        for (int oo = 0; oo < 8; oo++) s01[oo] = 0;

        #pragma unroll
        for (int j = 0; j < 9; j++) {
            int rr = j / 3;
            int wc = wcol[j % 3];
            const uint32_t* xp0 = &sx[rr][wc][0];
            uint4 xa = *(const uint4*)xp0;
            uint4 xb = *(const uint4*)(xp0 + 4);
            const uint32_t* xp1 = &sx[rr+1][wc][0];
            uint4 ya = *(const uint4*)xp1;
            uint4 yb = *(const uint4*)(xp1 + 4);
            #pragma unroll
            for (int oo = 0; oo < 8; oo++) {
                const uint4* wp = (const uint4*)(&sw[(ob + oo)*72 + j*8]);
                uint4 wa = wp[0];
                uint4 wb = wp[1];
                int t0 = tap_count(xa, xb, wa, wb);
                int t1 = tap_count(ya, yb, wa, wb);
                s01[oo] += t0 + (t1 << 16);
            }
        }

        #pragma unroll
        for (int oo = 0; oo < 8; oo++) {
            int o = oq*64 + ob + oo;
            int s0 = s01[oo] & 0xFFFF;
            int s1 = s01[oo] >> 16;
            int a0 = min(max(2304 - 2*s0, -254), 254);
            int a1 = min(max(2304 - 2*s1, -254), 254);
            size_t idx = base0 + (size_t)o * HW;
            if (MODE == 1) {
                if (valid) { g_y1b[idx] = (int8_t)(a0 >> 1); g_y1b[idx + Ww] = (int8_t)(a1 >> 1); }
                int vs = valid ? (a0 + a1) : 0;
                int vq = valid ? (a0*a0 + a1*a1) : 0;
                vs = __reduce_add_sync(0xffffffffu, vs);
                vq = __reduce_add_sync(0xffffffffu, vq);
                if (w == 0) { atomicAdd(&g_s1[o], vs); atomicAdd(&g_q1[o], vq); }
            } else {
                float z0 = 0.f, z1 = 0.f;
                if (valid) {
                    z0 = (float)a0 + x0res[idx];
                    z1 = (float)a1 + x0res[idx + Ww];
                    g_y2b[idx] = (int8_t)(a0 >> 1); g_y2b[idx + Ww] = (int8_t)(a1 >> 1);
                }
                float fs = z0 + z1, fq = z0*z0 + z1*z1;
                #pragma unroll
                for (int d = 16; d; d >>= 1) {
                    fs += __shfl_xor_sync(0xffffffffu, fs, d);
                    fq += __shfl_xor_sync(0xffffffffu, fq, d);
                }
                if (w == 0) { atomicAdd(&g_S2[o], (double)fs); atomicAdd(&g_Q2[o], (double)fq); }
            }
        }
    }
}

// ---------------- boundary conv v3: 8 pixels/block, shared wrT loads, smem tables ----------------
// per odd-V chunk: corr = 2*((P&1)^((V>>1)&1)) - 1 (banker's rounding, exact — verified r7)
// acc_final = SV - 2*sumP + 2*ccnt - NO
__device__ __forceinline__ void bstep(uint32_t& acc, unsigned long long s, unsigned long long w64,
                                      unsigned long long m, uint32_t v2, uint32_t od) {
    unsigned long long X = (s ^ w64) & m;
    uint32_t P = __popcll(X);
    uint32_t tt = (P ^ v2) & od;
    acc += P + (tt << 16);
}

template<int MODE>
__global__ void __launch_bounds__(256, 4) k_conv_bnd(const float* __restrict__ x0res, int slot) {
    int g = blockIdx.x & 15, n = blockIdx.x >> 4;   // 16 groups of 8 boundary pixels
    __shared__ unsigned long long s_vm[9*NCHUNK];
    __shared__ int                s_V[9*NCHUNK];
    __shared__ unsigned long long sxr[8][NCHUNK];
    __shared__ int                s_hw[8];          // (h<<16)|(w<<8)|cls
    int t = threadIdx.x, warp = t >> 5, lane = t & 31;

    for (int i = t; i < 9*NCHUNK; i += 256) { s_vm[i] = g_vmask[i]; s_V[i] = g_V[i]; }

    // warp k builds pixel p = g*8+k: 36 r-ordered chunk words via ballot
    int p = g*8 + warp;
    if (p < 124) {
        int h, w;
        if      (p < 32) { h = 0;      w = p; }
        else if (p < 64) { h = 31;     w = p - 32; }
        else if (p < 94) { w = 0;      h = p - 63; }
        else             { w = 31;     h = p - 93; }
        int ht = (h == 0) ? 0 : ((h == 31) ? 2 : 1);
        int wt = (w == 0) ? 0 : ((w == 31) ? 2 : 1);
        if (lane == 0) s_hw[warp] = (h << 16) | (w << 8) | (ht*3 + wt);
        for (int i = 0; i < NCHUNK; i++) {
            int r0 = 64*i + lane;
            int c0 = r0 / 9, j0 = r0 - 9*c0;
            int kh0 = j0 / 3, kw0 = j0 - 3*kh0;
            int hh0 = min(max(h + kh0 - 1, 0), 31), ww0 = min(max(w + kw0 - 1, 0), 31);
            unsigned lo = __ballot_sync(0xffffffffu,
                (g_xbits[((n*Hh + hh0)*Ww + ww0)*8 + (c0 >> 5)] >> (c0 & 31)) & 1u);
            int r1 = r0 + 32;
            int c1 = r1 / 9, j1 = r1 - 9*c1;
            int kh1 = j1 / 3, kw1 = j1 - 3*kh1;
            int hh1 = min(max(h + kh1 - 1, 0), 31), ww1 = min(max(w + kw1 - 1, 0), 31);
            unsigned hi = __ballot_sync(0xffffffffu,
                (g_xbits[((n*Hh + hh1)*Ww + ww1)*8 + (c1 >> 5)] >> (c1 & 31)) & 1u);
            if (lane == 0)
                sxr[warp][i] = (unsigned long long)lo | ((unsigned long long)hi << 32);
        }
    }
    __syncthreads();

    int o = t;                        // each thread owns one output channel for all 8 pixels
    int np = min(124 - g*8, 8);       // 8, except last group (4)
    int cb[8];                        // per-pixel class table base
    #pragma unroll
    for (int k = 0; k < 8; k++) cb[k] = (k < np) ? (s_hw[k] & 255) * NCHUNK : 0;

    uint32_t acc[8];
    #pragma unroll
    for (int k = 0; k < 8; k++) acc[k] = 0;

    const unsigned long long* wr = g_wrT[slot];
    for (int i = 0; i < NCHUNK; i++) {
        unsigned long long w64 = wr[i*Cc + o];    // one LDG serves 8 pixels
        #pragma unroll
        for (int k = 0; k < 8; k++) {
            if (k < np) {
                unsigned long long m = s_vm[cb[k] + i];
                int V = s_V[cb[k] + i];
                bstep(acc[k], sxr[k][i], w64, m, (uint32_t)((V >> 1) & 1), (uint32_t)(V & 1));
            }
        }
    }

    int    sumS = 0, sumQ = 0;
    double dz = 0.0, dq = 0.0;
    #pragma unroll
    for (int k = 0; k < 8; k++) {
        if (k < np) {
            int info = s_hw[k];
            int h = info >> 16, w = (info >> 8) & 255, ck = info & 255;
            int sumP = (int)(acc[k] & 0xFFFF);
            int ccnt = (int)(acc[k] >> 16);
            int a = g_SV[ck] - 2*sumP + 2*ccnt - g_NO[ck];
            a = min(max(a, -254), 254);
            size_t idx = ((size_t)(n*Cc + o) * Hh + h) * Ww + w;
            if (MODE == 1) {
                g_y1b[idx] = (int8_t)(a >> 1);
                sumS += a; sumQ += a*a;
            } else {
                float z = (float)a + x0res[idx];
                g_y2b[idx] = (int8_t)(a >> 1);
                dz += (double)z; dq += (double)(z*z);
            }
        }
    }
    if (MODE == 1) { atomicAdd(&g_s1[o], sumS); atomicAdd(&g_q1[o], sumQ); }
    else           { atomicAdd(&g_S2[o], dz);   atomicAdd(&g_Q2[o], dq); }
}

// ---------------- BN coefficient kernels ----------------
__global__ void k_coef1(const float* __restrict__ gamma, const float* __restrict__ beta) {
    int o = threadIdx.x;
    double m   = (double)g_s1[o] / (double)(Nn*HW);
    double var = (double)g_q1[o] / (double)(Nn*HW) - m*m;
    float inv  = (float)(1.0 / sqrt(var + 1e-5));
    float A = gamma[o] * inv;
    g_A1[o] = A;
    g_B1[o] = beta[o] - (float)m * A;
}

__global__ void k_coef2(const float* __restrict__ gamma, const float* __restrict__ beta) {
    int o = threadIdx.x;
    double m   = g_S2[o] / (double)(Nn*HW);
    double var = g_Q2[o] / (double)(Nn*HW) - m*m;
    float inv  = (float)(1.0 / sqrt(var + 1e-5));
    float A = gamma[o] * inv;
    g_A2[o] = A;
    g_B2[o] = beta[o] - (float)m * A;
}

// ---------------- finalize: z = 2*y2b + residual, bn2 + hardtanh, regularizer scalar ----------------
__global__ void k_final(float* __restrict__ out, const float* __restrict__ reg0,
                        const float* __restrict__ x0, int out_size) {
    size_t v = (size_t)blockIdx.x * 256 + threadIdx.x;   // 4-element group index
    size_t idx = v * 4;
    if (idx < (size_t)NCHW) {
        int o = (int)((idx >> 10) & 255);
        float A = g_A2[o], B = g_B2[o];
        char4 a = *(const char4*)(g_y2b + idx);
        float4 x = *(const float4*)(x0 + idx);
        float4 r;
        // z = (float)acc + x0 — bitwise identical to the value used in fused stats
        r.x = fminf(fmaxf(fmaf((float)(2*(int)a.x) + x.x, A, B), -1.f), 1.f);
        r.y = fminf(fmaxf(fmaf((float)(2*(int)a.y) + x.y, A, B), -1.f), 1.f);
        r.z = fminf(fmaxf(fmaf((float)(2*(int)a.z) + x.z, A, B), -1.f), 1.f);
        r.w = fminf(fmaxf(fmaf((float)(2*(int)a.w) + x.w, A, B), -1.f), 1.f);
        *(float4*)(out + idx) = r;
    }
    if (v == 0) out[out_size - 1] = reg0[0] + g_regbase;
}

// ---------------- launch ----------------
extern "C" void kernel_launch(void* const* d_in, const int* in_sizes, int n_in,
                              void* d_out, int out_size) {
    const float* x0   = (const float*)d_in[0];
    const float* reg0 = (const float*)d_in[1];
    const float* w1   = (const float*)d_in[2];
    const float* g1   = (const float*)d_in[3];
    const float* b1   = (const float*)d_in[4];
    const float* w2   = (const float*)d_in[5];
    const float* g2   = (const float*)d_in[6];
    const float* b2   = (const float*)d_in[7];
    float* out = (float*)d_out;

    k_init<<<1, 512>>>();                       // 0
    k_packw<<<512, 256>>>(w1, w2);              // 1
    k_pack_x<<<Nn*Hh, 256>>>(x0);               // 2
    k_conv_int<1><<<296, 256>>>(nullptr, 0);    // 3  persistent + work-stealing
    k_conv_bnd<1><<<Nn*16, 256>>>(nullptr, 0);  // 4  8 pixels/block
    k_coef1<<<1, Cc>>>(g1, b1);                 // 5
    k_pack2<<<Nn*Hh, 256>>>();                  // 6
    k_conv_int<2><<<296, 256>>>(x0, 1);         // 7
    k_conv_bnd<2><<<Nn*16, 256>>>(x0, 1);       // 8
    k_coef2<<<1, Cc>>>(g2, b2);                 // 9
    k_final<<<(NCHW/4 + 255) / 256, 256>>>(out, reg0, x0, out_size);  // 10
}